// round 17
// baseline (speedup 1.0000x reference)
#include <cuda_runtime.h>
#include <stdint.h>

#define NUM_NODES 100000
#define NUM_EDGES 400000
#define MAXR      26          // tag bound; rounds ~12-18
#define BLOCKS    148         // 1 block/SM (validated best config)
#define TPB       1024
#define NT        (BLOCKS * TPB)

typedef unsigned long long u64;

// Scratch (__device__ globals; no allocs). Cross-replay invariant:
// g_best == 0 and g_any == 0 at entry (end-of-replay clear below;
// g_dead / g_sd / labels / keys are re-initialized in the fused round-0 phase).
__device__ u64           g_key[NUM_EDGES];    // 51-bit key: score32<<19 | (524287-e)
__device__ int2          g_sd[NUM_EDGES];     // packed (src,dst)
__device__ int           g_label[NUM_NODES];
__device__ u64           g_best[NUM_NODES];   // tagged: round<<51 | key51
__device__ unsigned char g_dead[NUM_EDGES];   // 1 = endpoints share a component
__device__ int           g_any[MAXR];         // any live edge in slot r's A-part
__device__ unsigned      g_count = 0;         // barrier arrivals
__device__ unsigned      g_gen   = 0;         // barrier generation (wrap-safe)

// ---- software grid barrier (R13-validated lean flat version) ----
__device__ __forceinline__ unsigned ld_acq(const unsigned* p) {
    unsigned v;
    asm volatile("ld.acquire.gpu.u32 %0, [%1];" : "=r"(v) : "l"(p) : "memory");
    return v;
}
__device__ __forceinline__ void st_rel(unsigned* p, unsigned v) {
    asm volatile("st.release.gpu.u32 [%0], %1;" :: "l"(p), "r"(v) : "memory");
}
__device__ __forceinline__ void gbar() {
    __syncthreads();
    if (threadIdx.x == 0) {
        unsigned my = ld_acq(&g_gen);
        unsigned a;
        asm volatile("atom.add.release.gpu.u32 %0, [%1], 1;"
                     : "=r"(a) : "l"(&g_count) : "memory");
        if (a == BLOCKS - 1) {
            g_count = 0;                     // ordered by the st.release below
            st_rel(&g_gen, my + 1u);
        } else {
            while (ld_acq(&g_gen) == my) __nanosleep(32);
        }
    }
    __syncthreads();
}

// Chase to the round-r super-root, resolving round-r hooks IMPLICITLY from
// g_best (no explicit hook writes exist). Invariants at slot start: labels are
// flat to round-(r-1) roots; g_best[root] carries tag r for hooked roots.
// Safety under concurrency:
//  - label writes this slot are final super-roots -> jumps only to ancestors;
//  - tag-(r+1) atomicMax overwrites g_best only at super-roots, whose chase
//    terminates immediately either way;
//  - unique keys -> hook digraph has only mutual 2-cycles, caught by the
//    best-equality check and resolved to min(v, nxt).
__device__ __forceinline__ int chase(int x, int rr) {
    int v = x;
    #pragma unroll 1
    while (true) {
        int p = g_label[v];
        if (p != v) { v = p; continue; }       // explicit pointer
        u64 bk = g_best[v];
        if ((int)(bk >> 51) != rr) return v;   // no round-rr hook -> final root
        int e  = 524287 - (int)(bk & 0x7FFFFULL);
        int2 sd = g_sd[e];
        int la = g_label[sd.x];
        int lb = g_label[sd.y];
        int nxt = (la != v) ? la : lb;
        if (nxt == v) return v;                // everything collapsed onto v
        if (g_best[nxt] == bk)                 // mutual 2-cycle
            return (v < nxt) ? v : nxt;
        v = nxt;                               // follow hook chain
    }
}

__global__ void __launch_bounds__(TPB, 1)
boruvka_kernel(const float* __restrict__ s,
               const float* __restrict__ u,
               const int*   __restrict__ src,
               const int*   __restrict__ dst,
               float*       __restrict__ out)
{
    const int tid = blockIdx.x * TPB + threadIdx.x;

    // ========== fused init + round-1 best (labels are identity) ==========
    // Keys bitwise-match the JAX f32 pipeline (validated rel_err==0.0):
    //   score = 1/(1+expf(-s)) + (-logf(-logf(u+1e-9)+1e-9))
    {
        const u64 tag1 = 1ULL << 51;
        for (int e = tid; e < NUM_EDGES; e += NT) {
            float sp = 1.0f / (1.0f + expf(-s[e]));
            float gb = -logf(-logf(u[e] + 1e-9f) + 1e-9f);
            unsigned ub = __float_as_uint(sp + gb);
            ub = (ub & 0x80000000u) ? ~ub : (ub | 0x80000000u);  // order-preserving
            u64 key = ((u64)ub << 19) | (u64)(524287 - e);       // ties -> lowest idx
            g_key[e] = key;
            out[e] = 0.0f;
            int ra = src[e], rb = dst[e];
            g_sd[e] = make_int2(ra, rb);
            if (ra != rb) {
                g_dead[e] = 0;
                u64 kv = tag1 | key;
                atomicMax(&g_best[ra], kv);
                atomicMax(&g_best[rb], kv);
            } else {
                g_dead[e] = 1;     // self-loop: dead forever
            }
        }
        for (int i = tid; i < NUM_NODES; i += NT) g_label[i] = i;
    }
    gbar();

    // ========== ONE slot per round: mark + flatten + next-best ==========
    int r = 1;
    while (true) {
        // node part: mark accepted edges at tagged roots, then flatten.
        // Mark coverage: only super-roots (mutual minima) can have their best
        // overwritten by this slot's tag-(r+1) atomics; the mutual MAX partner
        // is never overwritten and also carries the same edge -> no edge lost.
        // Redundant out[e]=1.0f stores are idempotent (same value).
        for (int i = tid; i < NUM_NODES; i += NT) {
            if (g_label[i] == i) {             // only the owner writes label[i]
                u64 bk = g_best[i];
                if ((int)(bk >> 51) == r)
                    out[524287 - (int)(bk & 0x7FFFFULL)] = 1.0f;
            }
            g_label[i] = chase(i, r);          // flatten to round-r super-root
        }
        // edge part: per-super-component best via implicit-hook chases
        {
            const u64 ntag = ((u64)(r + 1)) << 51;
            bool live_any = false;
            for (int e = tid; e < NUM_EDGES; e += NT) {
                if (g_dead[e]) continue;
                int2 sd = g_sd[e];
                int ra = chase(sd.x, r);
                int rb = chase(sd.y, r);
                if (ra == rb) { g_dead[e] = 1; continue; }   // dead forever
                live_any = true;
                u64 kv = ntag | g_key[e];
                atomicMax(&g_best[ra], kv);
                atomicMax(&g_best[rb], kv);
            }
            if (live_any) g_any[r] = 1;        // idempotent racy store
        }
        gbar();
        // no live edges -> no tag-(r+1) hooks exist; all marks done -> exit
        if (!g_any[r]) break;
        if (++r >= MAXR) break;                // safety (never hit)
    }

    // ---- end-of-replay clear (stream order covers the next replay) ----
    for (int i = tid; i < NUM_NODES; i += NT) g_best[i] = 0ULL;
    if (tid < MAXR) g_any[tid] = 0;
}

extern "C" void kernel_launch(void* const* d_in, const int* in_sizes, int n_in,
                              void* d_out, int out_size)
{
    const float* s   = (const float*)d_in[0];
    const float* u   = (const float*)d_in[1];
    const int*   ei  = (const int*)d_in[2];   // [2, E] row-major
    const int*   src = ei;
    const int*   dst = ei + NUM_EDGES;
    float*       out = (float*)d_out;

    boruvka_kernel<<<BLOCKS, TPB>>>(s, u, src, dst, out);
}